// round 4
// baseline (speedup 1.0000x reference)
#include <cuda_runtime.h>
#include <math.h>

#define N_UTT 16384
#define DIM   256
#define WHALF 64
#define WIN   128   // 2*WHALF

// ---------------- scratch (device globals; no allocations allowed) ----------
__device__ float g_sup[5][N_UTT * DIM];   // [0]=x@W_att, [1]=pred, [2]=suc, [3]=same, [4]=diff
__device__ float g_attn[N_UTT * WIN];     // softmaxed attention, [N][128]
__device__ float g_h[N_UTT * DIM];        // aggregated hidden before log_softmax

// Packed fp32x2 FMA (sm_100+): d = a*b + d, two independent IEEE-RN lanes.
// ptxas never emits FFMA2 from C++; explicit PTX required (SASS_QUICKREF).
#define FFMA_F32X2(d, a, b) \
    asm("fma.rn.f32x2 %0, %1, %2, %0;" : "+l"(d) : "l"(a), "l"(b))
#define PACK_BCAST_F32X2(d, s) \
    asm("mov.b64 %0, {%1, %1};" : "=l"(d) : "r"(__float_as_uint(s)))

// ============================================================================
// K1: C[z] = A @ B[z],  A:[N,256] row-major, B:[256,256] row-major, z=0..4
// 128x128 tile, BK=16, 256 threads, 8x8 microtile per thread, f32x2 packed FMA.
// ============================================================================
__global__ __launch_bounds__(256) void gemm5_kernel(
    const float* __restrict__ A,
    const float* __restrict__ B0, const float* __restrict__ B1,
    const float* __restrict__ B2, const float* __restrict__ B3,
    const float* __restrict__ B4)
{
    const int z = blockIdx.z;
    const float* B = (z == 0) ? B0 : (z == 1) ? B1 : (z == 2) ? B2 : (z == 3) ? B3 : B4;
    float* C = g_sup[z];

    const int i0 = blockIdx.x * 128;   // row block
    const int n0 = blockIdx.y * 128;   // col block

    __shared__ float As[16][128];      // [k][m] (A transposed into smem)
    __shared__ float Bs[16][128];      // [k][n]

    const int tid = threadIdx.x;
    const int tx = tid & 15;           // col group (8 cols each)
    const int ty = tid >> 4;           // row group (8 rows each)

    // acc2[m][n2] = packed (C[m][2*n2], C[m][2*n2+1])
    unsigned long long acc2[8][4];
#pragma unroll
    for (int m = 0; m < 8; m++)
#pragma unroll
        for (int n2 = 0; n2 < 4; n2++) acc2[m][n2] = 0ull;

    for (int kk = 0; kk < DIM; kk += 16) {
        // load A tile: 128 rows x 16 k  (512 float4)
#pragma unroll
        for (int q = 0; q < 2; q++) {
            int idx = tid + q * 256;           // 0..511
            int r = idx >> 2;                  // 0..127
            int c4 = (idx & 3) * 4;            // 0,4,8,12
            float4 av = *(const float4*)(A + (size_t)(i0 + r) * DIM + kk + c4);
            As[c4 + 0][r] = av.x;
            As[c4 + 1][r] = av.y;
            As[c4 + 2][r] = av.z;
            As[c4 + 3][r] = av.w;
        }
        // load B tile: 16 k x 128 n (512 float4)
#pragma unroll
        for (int q = 0; q < 2; q++) {
            int idx = tid + q * 256;
            int r = idx >> 5;                  // 0..15
            int c4 = (idx & 31) * 4;           // 0..124
            float4 bv = *(const float4*)(B + (size_t)(kk + r) * DIM + n0 + c4);
            *(float4*)&Bs[r][c4] = bv;
        }
        __syncthreads();

#pragma unroll
        for (int k = 0; k < 16; k++) {
            float a[8];
            *(float4*)&a[0] = *(float4*)&As[k][ty * 8];
            *(float4*)&a[4] = *(float4*)&As[k][ty * 8 + 4];
            // b as packed pairs straight out of the LDS.128 register quads
            unsigned long long b2[4];
            {
                ulonglong2 t0 = *(ulonglong2*)&Bs[k][tx * 8];
                ulonglong2 t1 = *(ulonglong2*)&Bs[k][tx * 8 + 4];
                b2[0] = t0.x; b2[1] = t0.y; b2[2] = t1.x; b2[3] = t1.y;
            }
#pragma unroll
            for (int m = 0; m < 8; m++) {
                unsigned long long am2;
                PACK_BCAST_F32X2(am2, a[m]);
#pragma unroll
                for (int n2 = 0; n2 < 4; n2++)
                    FFMA_F32X2(acc2[m][n2], am2, b2[n2]);
            }
        }
        __syncthreads();
    }

#pragma unroll
    for (int m = 0; m < 8; m++) {
        float2 c0 = *(float2*)&acc2[m][0];
        float2 c1 = *(float2*)&acc2[m][1];
        float2 c2 = *(float2*)&acc2[m][2];
        float2 c3 = *(float2*)&acc2[m][3];
        size_t row = (size_t)(i0 + ty * 8 + m) * DIM + n0 + tx * 8;
        *(float4*)(C + row)     = make_float4(c0.x, c0.y, c1.x, c1.y);
        *(float4*)(C + row + 4) = make_float4(c2.x, c2.y, c3.x, c3.y);
    }
}

// ============================================================================
// K2: raw[i,w] = x[i+w-64] . y[i]  (zero-padded outside [0,N)), then softmax
// over w=0..127 (padded slots contribute raw=0, included, matching reference).
// Block handles 64 consecutive i. 256 threads: w = t&127, ihalf = t>>7,
// each thread accumulates rows i_loc = ihalf + 2k, k=0..31.
// SMEM: xs[192][36] window chunk, ys[64][36] y chunk (pad 36 for LDS.128).
// ============================================================================
#define K2_TI 64
__global__ __launch_bounds__(256) void attn_kernel(
    const float* __restrict__ x, int N)
{
    __shared__ float smem[192 * 36 + 64 * 36];   // 36864 B
    float* xs = smem;                 // [192][36]
    float* ys = smem + 192 * 36;      // [64][36]

    const float* y = g_sup[0];
    const int i0 = blockIdx.x * K2_TI;
    const int t = threadIdx.x;
    const int w = t & 127;
    const int ihalf = t >> 7;

    float acc[32];
#pragma unroll
    for (int k = 0; k < 32; k++) acc[k] = 0.f;

    for (int dc = 0; dc < DIM; dc += 32) {
        // ys: 64 x 32 = 512 float4
        for (int e = t; e < 64 * 8; e += 256) {
            int r = e >> 3, c4 = (e & 7) * 4;
            *(float4*)&ys[r * 36 + c4] =
                *(const float4*)(y + (size_t)(i0 + r) * DIM + dc + c4);
        }
        // xs: 192 x 32 = 1536 float4, zero-padded rows outside [0,N)
        for (int e = t; e < 192 * 8; e += 256) {
            int r = e >> 3, c4 = (e & 7) * 4;
            int j = i0 - WHALF + r;
            float4 v = make_float4(0.f, 0.f, 0.f, 0.f);
            if (j >= 0 && j < N)
                v = *(const float4*)(x + (size_t)j * DIM + dc + c4);
            *(float4*)&xs[r * 36 + c4] = v;
        }
        __syncthreads();

        for (int c4 = 0; c4 < 8; c4++) {
#pragma unroll
            for (int k = 0; k < 32; k++) {
                int il = ihalf + 2 * k;
                float4 xv = *(float4*)&xs[(il + w) * 36 + c4 * 4];
                float4 yv = *(float4*)&ys[il * 36 + c4 * 4];
                acc[k] += xv.x * yv.x + xv.y * yv.y + xv.z * yv.z + xv.w * yv.w;
            }
        }
        __syncthreads();
    }

    // write raw into smem (reuse) and softmax per row
    float* raw = smem;   // [64][128]
#pragma unroll
    for (int k = 0; k < 32; k++)
        raw[(ihalf + 2 * k) * WIN + w] = acc[k];
    __syncthreads();

    const int wid = t >> 5, lane = t & 31;
#pragma unroll
    for (int rr = 0; rr < 8; rr++) {
        int i = wid * 8 + rr;
        float v0 = raw[i * WIN + lane];
        float v1 = raw[i * WIN + lane + 32];
        float v2 = raw[i * WIN + lane + 64];
        float v3 = raw[i * WIN + lane + 96];
        float mx = fmaxf(fmaxf(v0, v1), fmaxf(v2, v3));
#pragma unroll
        for (int o = 16; o; o >>= 1)
            mx = fmaxf(mx, __shfl_xor_sync(0xffffffffu, mx, o));
        float e0 = expf(v0 - mx), e1 = expf(v1 - mx);
        float e2 = expf(v2 - mx), e3 = expf(v3 - mx);
        float s = e0 + e1 + e2 + e3;
#pragma unroll
        for (int o = 16; o; o >>= 1)
            s += __shfl_xor_sync(0xffffffffu, s, o);
        float inv = 1.f / s;
        size_t base = (size_t)(i0 + i) * WIN;
        g_attn[base + lane] = e0 * inv;
        g_attn[base + lane + 32] = e1 * inv;
        g_attn[base + lane + 64] = e2 * inv;
        g_attn[base + lane + 96] = e3 * inv;
    }
}

// ============================================================================
// K3: h[i] = sum_w a[i,w] * ( (off>=0 ? pred : suc)[j] + (same_spk ? same : diff)[j] )
//   restructured as: c_base*( (pred|suc)[j] + diff[j] ) + c_eq*( same[j]-diff[j] )
// j-major: each support row loaded ONCE per 32-row tile.
// Block: 32 rows, 128 threads, each thread owns a float2 column pair.
// ============================================================================
#define K3_TI 32
#define K3_JW 160   // j window per tile: [i0-64, i0+95]
__global__ __launch_bounds__(128) void agg_kernel(
    const int* __restrict__ spk, int N)
{
    __shared__ float c_base[K3_TI * K3_JW];
    __shared__ float c_eq[K3_TI * K3_JW];

    const int i0 = blockIdx.x * K3_TI;
    const int t = threadIdx.x;

    // prologue: coefficients
    for (int e = t; e < K3_TI * K3_JW; e += 128) {
        int i = e / K3_JW;
        int jj = e - i * K3_JW;
        int j = i0 - WHALF + jj;
        int w = jj - i;                       // w = j - (i0+i) + 64
        bool ok = (w >= 0) && (w < WIN) && (j >= 0) && (j < N);
        float a = ok ? g_attn[(size_t)(i0 + i) * WIN + w] : 0.f;
        c_base[e] = a;
        c_eq[e] = (ok && spk[j] == spk[i0 + i]) ? a : 0.f;
    }
    __syncthreads();

    const float* P  = g_sup[1];
    const float* S  = g_sup[2];
    const float* SM = g_sup[3];
    const float* DF = g_sup[4];
    const int d2 = t * 2;

    float2 acc[K3_TI];
#pragma unroll
    for (int i = 0; i < K3_TI; i++) { acc[i].x = 0.f; acc[i].y = 0.f; }

    for (int jj = 0; jj < K3_JW; jj++) {
        int j = i0 - WHALF + jj;
        if (j < 0 || j >= N) continue;
        size_t idx = (size_t)j * DIM + d2;
        float2 p  = *(const float2*)(P + idx);
        float2 s  = *(const float2*)(S + idx);
        float2 sm = *(const float2*)(SM + idx);
        float2 df = *(const float2*)(DF + idx);
        float2 diff = make_float2(sm.x - df.x, sm.y - df.y);
        float2 pd   = make_float2(p.x + df.x, p.y + df.y);
        float2 sd   = make_float2(s.x + df.x, s.y + df.y);
        int isplit = jj - WHALF;   // i <= isplit -> pred branch (off >= 0)
#pragma unroll
        for (int i = 0; i < K3_TI; i++) {
            float c  = c_base[i * K3_JW + jj];
            float ce = c_eq[i * K3_JW + jj];
            bool pred = (i <= isplit);
            float bx = pred ? pd.x : sd.x;
            float by = pred ? pd.y : sd.y;
            acc[i].x += c * bx + ce * diff.x;
            acc[i].y += c * by + ce * diff.y;
        }
    }

#pragma unroll
    for (int i = 0; i < K3_TI; i++)
        *(float2*)(g_h + (size_t)(i0 + i) * DIM + d2) = acc[i];
}

// ============================================================================
// K4: row-wise log_softmax over D=256. One block (256 threads) per row.
// ============================================================================
__global__ __launch_bounds__(256) void lsm_kernel(float* __restrict__ out)
{
    __shared__ float red[8];
    __shared__ float bcast;

    const int i = blockIdx.x;
    const int t = threadIdx.x;
    const int wid = t >> 5, lane = t & 31;

    float v = g_h[(size_t)i * DIM + t];

    // block max
    float m = v;
#pragma unroll
    for (int o = 16; o; o >>= 1)
        m = fmaxf(m, __shfl_xor_sync(0xffffffffu, m, o));
    if (lane == 0) red[wid] = m;
    __syncthreads();
    if (t < 32) {
        float xr = (t < 8) ? red[t] : -INFINITY;
#pragma unroll
        for (int o = 4; o; o >>= 1)
            xr = fmaxf(xr, __shfl_xor_sync(0xffffffffu, xr, o));
        if (t == 0) bcast = xr;
    }
    __syncthreads();
    float mx = bcast;

    // block sum of exp
    float e = expf(v - mx);
    float sum = e;
#pragma unroll
    for (int o = 16; o; o >>= 1)
        sum += __shfl_xor_sync(0xffffffffu, sum, o);
    if (lane == 0) red[wid] = sum;
    __syncthreads();
    if (t < 32) {
        float xr = (t < 8) ? red[t] : 0.f;
#pragma unroll
        for (int o = 4; o; o >>= 1)
            xr += __shfl_xor_sync(0xffffffffu, xr, o);
        if (t == 0) bcast = logf(xr);
    }
    __syncthreads();
    float lse = bcast;

    out[(size_t)i * DIM + t] = v - mx - lse;
}

// ============================================================================
// launch
// ============================================================================
extern "C" void kernel_launch(void* const* d_in, const int* in_sizes, int n_in,
                              void* d_out, int out_size)
{
    const float* x      = (const float*)d_in[0];
    const int*   spk    = (const int*)d_in[1];
    const float* W_att  = (const float*)d_in[2];
    const float* W_pred = (const float*)d_in[3];
    const float* W_suc  = (const float*)d_in[4];
    const float* W_same = (const float*)d_in[5];
    const float* W_diff = (const float*)d_in[6];
    float* out = (float*)d_out;

    const int N = in_sizes[1];   // speaker_ids element count == N

    // K1: 5 GEMMs (y_att + 4 supports)
    {
        dim3 grid(N / 128, DIM / 128, 5);
        gemm5_kernel<<<grid, 256>>>(x, W_att, W_pred, W_suc, W_same, W_diff);
    }
    // K2: banded attention + softmax
    attn_kernel<<<N / K2_TI, 256>>>(x, N);
    // K3: banded relation aggregation
    agg_kernel<<<N / K3_TI, 128>>>(spk, N);
    // K4: log_softmax
    lsm_kernel<<<N, 256>>>(out);
}

// round 11
// speedup vs baseline: 1.2573x; 1.2573x over previous
#include <cuda_runtime.h>
#include <cuda_bf16.h>
#include <math.h>

#define N_UTT 16384
#define DIM   256
#define WHALF 64
#define WIN   128   // 2*WHALF

// ---------------- scratch (device globals; no allocations allowed) ----------
__device__ float g_sup[5][N_UTT * DIM];   // [0]=x@W_att, [1]=pred, [2]=suc, [3]=same, [4]=diff
__device__ float g_attn[N_UTT * WIN];     // softmaxed attention, [N][128]
__device__ float g_h[N_UTT * DIM];        // aggregated hidden before log_softmax
// bf16 hi/lo splits for the HMMA GEMM
__device__ __nv_bfloat16 g_xhi[N_UTT * DIM];
__device__ __nv_bfloat16 g_xlo[N_UTT * DIM];
__device__ __nv_bfloat16 g_whi[5 * DIM * DIM];   // [z][n][k] = bf16(W_z[k][n])  (col-major B)
__device__ __nv_bfloat16 g_wlo[5 * DIM * DIM];

// mma.sync m16n8k16 bf16 (sm_80+ baseline PTX, no arch-variant features)
#define MMA16816(c, a, b)                                                       \
    asm volatile("mma.sync.aligned.m16n8k16.row.col.f32.bf16.bf16.f32 "         \
        "{%0,%1,%2,%3}, {%4,%5,%6,%7}, {%8,%9}, {%0,%1,%2,%3};"                 \
        : "+f"((c)[0]), "+f"((c)[1]), "+f"((c)[2]), "+f"((c)[3])                \
        : "r"((a)[0]), "r"((a)[1]), "r"((a)[2]), "r"((a)[3]),                   \
          "r"((b)[0]), "r"((b)[1]))

// ============================================================================
// P1: x -> (hi, lo) bf16 split.  4 floats per thread.
// ============================================================================
__global__ __launch_bounds__(256) void conv_x_kernel(const float* __restrict__ x)
{
    int i4 = blockIdx.x * 256 + threadIdx.x;     // 0 .. N*D/4-1
    float4 v = ((const float4*)x)[i4];
    __nv_bfloat16 h0 = __float2bfloat16(v.x), h1 = __float2bfloat16(v.y);
    __nv_bfloat16 h2 = __float2bfloat16(v.z), h3 = __float2bfloat16(v.w);
    __nv_bfloat16 l0 = __float2bfloat16(v.x - __bfloat162float(h0));
    __nv_bfloat16 l1 = __float2bfloat16(v.y - __bfloat162float(h1));
    __nv_bfloat16 l2 = __float2bfloat16(v.z - __bfloat162float(h2));
    __nv_bfloat16 l3 = __float2bfloat16(v.w - __bfloat162float(h3));
    ((__nv_bfloat162*)g_xhi)[i4 * 2]     = __nv_bfloat162(h0, h1);
    ((__nv_bfloat162*)g_xhi)[i4 * 2 + 1] = __nv_bfloat162(h2, h3);
    ((__nv_bfloat162*)g_xlo)[i4 * 2]     = __nv_bfloat162(l0, l1);
    ((__nv_bfloat162*)g_xlo)[i4 * 2 + 1] = __nv_bfloat162(l2, l3);
}

// ============================================================================
// P2: W_z -> transposed (hi, lo) bf16: g_w*[z][n][k] = split(W_z[k][n]).
// ============================================================================
__global__ __launch_bounds__(256) void conv_w_kernel(
    const float* __restrict__ W0, const float* __restrict__ W1,
    const float* __restrict__ W2, const float* __restrict__ W3,
    const float* __restrict__ W4)
{
    int id = blockIdx.x * 256 + threadIdx.x;     // 0 .. 5*256*256-1
    int z = id >> 16, rem = id & 65535;
    int n = rem >> 8, k = rem & 255;
    const float* W = (z == 0) ? W0 : (z == 1) ? W1 : (z == 2) ? W2 : (z == 3) ? W3 : W4;
    float v = W[k * DIM + n];
    __nv_bfloat16 h = __float2bfloat16(v);
    g_whi[id] = h;
    g_wlo[id] = __float2bfloat16(v - __bfloat162float(h));
}

// ============================================================================
// K1: HMMA GEMM.  C[z] (16384x256) = x @ W_z via 3-term bf16 split
//     (Ah*Bh + Ah*Bl + Al*Bh, fp32 accumulate).
// CTA: 128x128 output tile, 8 warps (warp tile 32x64), K chunks of 32.
// SMEM: A/B hi+lo, row stride 40 bf16 -> conflict-free fragment LDS.
// ============================================================================
#define KK 32
#define AS 40    // smem row stride in bf16 (80B); frag banks 20r+q all distinct
#define SM_ELE (128 * AS)

__global__ __launch_bounds__(256) void gemm_mma_kernel()
{
    __shared__ __nv_bfloat16 sm[4 * SM_ELE];   // 40960 bytes
    __nv_bfloat16* sAh = sm;
    __nv_bfloat16* sAl = sm + SM_ELE;
    __nv_bfloat16* sBh = sm + 2 * SM_ELE;
    __nv_bfloat16* sBl = sm + 3 * SM_ELE;

    const int tid = threadIdx.x;
    const int warp = tid >> 5, lane = tid & 31;
    const int g = lane >> 2, tg = lane & 3;    // groupID / threadID-in-group
    const int wm = warp & 3, wn = warp >> 2;   // 4x2 warp grid

    const int m0 = blockIdx.x * 128;
    const int n0 = blockIdx.y * 128;
    const int z = blockIdx.z;
    const size_t wbase = (size_t)z * DIM * DIM;

    float c[2][8][4];
#pragma unroll
    for (int mf = 0; mf < 2; mf++)
#pragma unroll
        for (int nf = 0; nf < 8; nf++)
#pragma unroll
            for (int q = 0; q < 4; q++) c[mf][nf][q] = 0.f;

    for (int k0 = 0; k0 < DIM; k0 += KK) {
        // fill: each buffer 128 rows x 32 k = 512 uint4
#pragma unroll
        for (int q = 0; q < 2; q++) {
            int e = tid + q * 256;             // 0..511
            int r = e >> 2, kq = (e & 3) * 8;  // row, k-offset (bf16 units)
            int so = r * AS + kq;
            size_t ga = (size_t)(m0 + r) * DIM + k0 + kq;
            size_t gb = wbase + (size_t)(n0 + r) * DIM + k0 + kq;
            *(uint4*)&sAh[so] = *(const uint4*)&g_xhi[ga];
            *(uint4*)&sAl[so] = *(const uint4*)&g_xlo[ga];
            *(uint4*)&sBh[so] = *(const uint4*)&g_whi[gb];
            *(uint4*)&sBl[so] = *(const uint4*)&g_wlo[gb];
        }
        __syncthreads();

#pragma unroll
        for (int ks = 0; ks < KK; ks += 16) {
            // B fragments for this warp's 8 n-frags (k16 x n8 each)
            unsigned bh[8][2], bl[8][2];
#pragma unroll
            for (int nf = 0; nf < 8; nf++) {
                int bn = wn * 64 + nf * 8 + g;
                int bk = ks + tg * 2;
                int o = bn * AS + bk;
                bh[nf][0] = *(const unsigned*)&sBh[o];
                bh[nf][1] = *(const unsigned*)&sBh[o + 8];
                bl[nf][0] = *(const unsigned*)&sBl[o];
                bl[nf][1] = *(const unsigned*)&sBl[o + 8];
            }
#pragma unroll
            for (int mf = 0; mf < 2; mf++) {
                int ar = wm * 32 + mf * 16 + g;
                int ak = ks + tg * 2;
                int o = ar * AS + ak;
                unsigned ah[4], al[4];
                ah[0] = *(const unsigned*)&sAh[o];
                ah[1] = *(const unsigned*)&sAh[o + 8 * AS];
                ah[2] = *(const unsigned*)&sAh[o + 8];
                ah[3] = *(const unsigned*)&sAh[o + 8 * AS + 8];
                al[0] = *(const unsigned*)&sAl[o];
                al[1] = *(const unsigned*)&sAl[o + 8 * AS];
                al[2] = *(const unsigned*)&sAl[o + 8];
                al[3] = *(const unsigned*)&sAl[o + 8 * AS + 8];
#pragma unroll
                for (int nf = 0; nf < 8; nf++) {
                    MMA16816(c[mf][nf], ah, bh[nf]);
                    MMA16816(c[mf][nf], ah, bl[nf]);
                    MMA16816(c[mf][nf], al, bh[nf]);
                }
            }
        }
        __syncthreads();
    }

    // epilogue: c0,c1 -> (row, col..col+1); c2,c3 -> (row+8, ...)
    float* C = g_sup[z];
#pragma unroll
    for (int mf = 0; mf < 2; mf++) {
#pragma unroll
        for (int nf = 0; nf < 8; nf++) {
            int row = m0 + wm * 32 + mf * 16 + g;
            int col = n0 + wn * 64 + nf * 8 + tg * 2;
            *(float2*)&C[(size_t)row * DIM + col] =
                make_float2(c[mf][nf][0], c[mf][nf][1]);
            *(float2*)&C[(size_t)(row + 8) * DIM + col] =
                make_float2(c[mf][nf][2], c[mf][nf][3]);
        }
    }
}

// ============================================================================
// K2: raw[i,w] = x[i+w-64] . y[i]  (zero-padded), then softmax over 128 slots.
// ============================================================================
#define K2_TI 64
__global__ __launch_bounds__(256) void attn_kernel(
    const float* __restrict__ x, int N)
{
    __shared__ float smem[192 * 36 + 64 * 36];
    float* xs = smem;
    float* ys = smem + 192 * 36;

    const float* y = g_sup[0];
    const int i0 = blockIdx.x * K2_TI;
    const int t = threadIdx.x;
    const int w = t & 127;
    const int ihalf = t >> 7;

    float acc[32];
#pragma unroll
    for (int k = 0; k < 32; k++) acc[k] = 0.f;

    for (int dc = 0; dc < DIM; dc += 32) {
        for (int e = t; e < 64 * 8; e += 256) {
            int r = e >> 3, c4 = (e & 7) * 4;
            *(float4*)&ys[r * 36 + c4] =
                *(const float4*)(y + (size_t)(i0 + r) * DIM + dc + c4);
        }
        for (int e = t; e < 192 * 8; e += 256) {
            int r = e >> 3, c4 = (e & 7) * 4;
            int j = i0 - WHALF + r;
            float4 v = make_float4(0.f, 0.f, 0.f, 0.f);
            if (j >= 0 && j < N)
                v = *(const float4*)(x + (size_t)j * DIM + dc + c4);
            *(float4*)&xs[r * 36 + c4] = v;
        }
        __syncthreads();

        for (int c4 = 0; c4 < 8; c4++) {
#pragma unroll
            for (int k = 0; k < 32; k++) {
                int il = ihalf + 2 * k;
                float4 xv = *(float4*)&xs[(il + w) * 36 + c4 * 4];
                float4 yv = *(float4*)&ys[il * 36 + c4 * 4];
                acc[k] += xv.x * yv.x + xv.y * yv.y + xv.z * yv.z + xv.w * yv.w;
            }
        }
        __syncthreads();
    }

    float* raw = smem;
#pragma unroll
    for (int k = 0; k < 32; k++)
        raw[(ihalf + 2 * k) * WIN + w] = acc[k];
    __syncthreads();

    const int wid = t >> 5, lane = t & 31;
#pragma unroll
    for (int rr = 0; rr < 8; rr++) {
        int i = wid * 8 + rr;
        float v0 = raw[i * WIN + lane];
        float v1 = raw[i * WIN + lane + 32];
        float v2 = raw[i * WIN + lane + 64];
        float v3 = raw[i * WIN + lane + 96];
        float mx = fmaxf(fmaxf(v0, v1), fmaxf(v2, v3));
#pragma unroll
        for (int o = 16; o; o >>= 1)
            mx = fmaxf(mx, __shfl_xor_sync(0xffffffffu, mx, o));
        float e0 = expf(v0 - mx), e1 = expf(v1 - mx);
        float e2 = expf(v2 - mx), e3 = expf(v3 - mx);
        float s = e0 + e1 + e2 + e3;
#pragma unroll
        for (int o = 16; o; o >>= 1)
            s += __shfl_xor_sync(0xffffffffu, s, o);
        float inv = 1.f / s;
        size_t base = (size_t)(i0 + i) * WIN;
        g_attn[base + lane] = e0 * inv;
        g_attn[base + lane + 32] = e1 * inv;
        g_attn[base + lane + 64] = e2 * inv;
        g_attn[base + lane + 96] = e3 * inv;
    }
}

// ============================================================================
// K3: banded relation aggregation (j-major, supports loaded once per tile).
// ============================================================================
#define K3_TI 32
#define K3_JW 160
__global__ __launch_bounds__(128) void agg_kernel(
    const int* __restrict__ spk, int N)
{
    __shared__ float c_base[K3_TI * K3_JW];
    __shared__ float c_eq[K3_TI * K3_JW];

    const int i0 = blockIdx.x * K3_TI;
    const int t = threadIdx.x;

    for (int e = t; e < K3_TI * K3_JW; e += 128) {
        int i = e / K3_JW;
        int jj = e - i * K3_JW;
        int j = i0 - WHALF + jj;
        int w = jj - i;
        bool ok = (w >= 0) && (w < WIN) && (j >= 0) && (j < N);
        float a = ok ? g_attn[(size_t)(i0 + i) * WIN + w] : 0.f;
        c_base[e] = a;
        c_eq[e] = (ok && spk[j] == spk[i0 + i]) ? a : 0.f;
    }
    __syncthreads();

    const float* P  = g_sup[1];
    const float* S  = g_sup[2];
    const float* SM = g_sup[3];
    const float* DF = g_sup[4];
    const int d2 = t * 2;

    float2 acc[K3_TI];
#pragma unroll
    for (int i = 0; i < K3_TI; i++) { acc[i].x = 0.f; acc[i].y = 0.f; }

    for (int jj = 0; jj < K3_JW; jj++) {
        int j = i0 - WHALF + jj;
        if (j < 0 || j >= N) continue;
        size_t idx = (size_t)j * DIM + d2;
        float2 p  = *(const float2*)(P + idx);
        float2 s  = *(const float2*)(S + idx);
        float2 sm = *(const float2*)(SM + idx);
        float2 df = *(const float2*)(DF + idx);
        float2 diff = make_float2(sm.x - df.x, sm.y - df.y);
        float2 pd   = make_float2(p.x + df.x, p.y + df.y);
        float2 sd   = make_float2(s.x + df.x, s.y + df.y);
        int isplit = jj - WHALF;
#pragma unroll
        for (int i = 0; i < K3_TI; i++) {
            float c  = c_base[i * K3_JW + jj];
            float ce = c_eq[i * K3_JW + jj];
            bool pred = (i <= isplit);
            float bx = pred ? pd.x : sd.x;
            float by = pred ? pd.y : sd.y;
            acc[i].x += c * bx + ce * diff.x;
            acc[i].y += c * by + ce * diff.y;
        }
    }

#pragma unroll
    for (int i = 0; i < K3_TI; i++)
        *(float2*)(g_h + (size_t)(i0 + i) * DIM + d2) = acc[i];
}

// ============================================================================
// K4: row-wise log_softmax over D=256.
// ============================================================================
__global__ __launch_bounds__(256) void lsm_kernel(float* __restrict__ out)
{
    __shared__ float red[8];
    __shared__ float bcast;

    const int i = blockIdx.x;
    const int t = threadIdx.x;
    const int wid = t >> 5, lane = t & 31;

    float v = g_h[(size_t)i * DIM + t];

    float m = v;
#pragma unroll
    for (int o = 16; o; o >>= 1)
        m = fmaxf(m, __shfl_xor_sync(0xffffffffu, m, o));
    if (lane == 0) red[wid] = m;
    __syncthreads();
    if (t < 32) {
        float xr = (t < 8) ? red[t] : -INFINITY;
#pragma unroll
        for (int o = 4; o; o >>= 1)
            xr = fmaxf(xr, __shfl_xor_sync(0xffffffffu, xr, o));
        if (t == 0) bcast = xr;
    }
    __syncthreads();
    float mx = bcast;

    float e = expf(v - mx);
    float sum = e;
#pragma unroll
    for (int o = 16; o; o >>= 1)
        sum += __shfl_xor_sync(0xffffffffu, sum, o);
    if (lane == 0) red[wid] = sum;
    __syncthreads();
    if (t < 32) {
        float xr = (t < 8) ? red[t] : 0.f;
#pragma unroll
        for (int o = 4; o; o >>= 1)
            xr += __shfl_xor_sync(0xffffffffu, xr, o);
        if (t == 0) bcast = logf(xr);
    }
    __syncthreads();
    float lse = bcast;

    out[(size_t)i * DIM + t] = v - mx - lse;
}

// ============================================================================
// launch
// ============================================================================
extern "C" void kernel_launch(void* const* d_in, const int* in_sizes, int n_in,
                              void* d_out, int out_size)
{
    const float* x      = (const float*)d_in[0];
    const int*   spk    = (const int*)d_in[1];
    const float* W_att  = (const float*)d_in[2];
    const float* W_pred = (const float*)d_in[3];
    const float* W_suc  = (const float*)d_in[4];
    const float* W_same = (const float*)d_in[5];
    const float* W_diff = (const float*)d_in[6];
    float* out = (float*)d_out;

    const int N = in_sizes[1];   // speaker_ids element count == N

    // P1/P2: bf16 hi/lo conversions
    conv_x_kernel<<<(N * DIM / 4) / 256, 256>>>(x);
    conv_w_kernel<<<(5 * DIM * DIM) / 256, 256>>>(W_att, W_pred, W_suc, W_same, W_diff);

    // K1: HMMA GEMMs (y_att + 4 supports)
    {
        dim3 grid(N / 128, DIM / 128, 5);
        gemm_mma_kernel<<<grid, 256>>>();
    }
    // K2: banded attention + softmax
    attn_kernel<<<N / K2_TI, 256>>>(x, N);
    // K3: banded relation aggregation
    agg_kernel<<<N / K3_TI, 128>>>(spk, N);
    // K4: log_softmax
    lsm_kernel<<<N, 256>>>(out);
}

// round 17
// speedup vs baseline: 1.6017x; 1.2739x over previous
#include <cuda_runtime.h>
#include <cuda_bf16.h>
#include <math.h>

#define N_UTT 16384
#define DIM   256
#define WHALF 64
#define WIN   128   // 2*WHALF

// ---------------- scratch (device globals; no allocations allowed) ----------
__device__ float g_sup[5][N_UTT * DIM];   // [0]=x@W_att, [1]=pred, [2]=suc, [3]=same, [4]=diff
__device__ float g_raw[N_UTT * DIM];      // dense attn products M [N][256]
__device__ float g_attn[N_UTT * WIN];     // softmaxed attention, [N][128]
__device__ float g_h[N_UTT * DIM];        // aggregated hidden before log_softmax
// bf16 hi/lo splits
__device__ __nv_bfloat16 g_xhi[N_UTT * DIM];
__device__ __nv_bfloat16 g_xlo[N_UTT * DIM];
__device__ __nv_bfloat16 g_yhi[N_UTT * DIM];
__device__ __nv_bfloat16 g_ylo[N_UTT * DIM];
__device__ __nv_bfloat16 g_whi[5 * DIM * DIM];   // [z][n][k] = bf16(W_z[k][n])  (col-major B)
__device__ __nv_bfloat16 g_wlo[5 * DIM * DIM];

// mma.sync m16n8k16 bf16 (sm_80+ baseline PTX, no arch-variant features)
#define MMA16816(c, a, b)                                                       \
    asm volatile("mma.sync.aligned.m16n8k16.row.col.f32.bf16.bf16.f32 "         \
        "{%0,%1,%2,%3}, {%4,%5,%6,%7}, {%8,%9}, {%0,%1,%2,%3};"                 \
        : "+f"((c)[0]), "+f"((c)[1]), "+f"((c)[2]), "+f"((c)[3])                \
        : "r"((a)[0]), "r"((a)[1]), "r"((a)[2]), "r"((a)[3]),                   \
          "r"((b)[0]), "r"((b)[1]))

__device__ __forceinline__ unsigned smem_u32(const void* p) {
    unsigned a;
    asm("{ .reg .u64 t; cvta.to.shared.u64 t, %1; cvt.u32.u64 %0, t; }"
        : "=r"(a) : "l"(p));
    return a;
}
// cp.async 16B with zero-fill when invalid (src-size = 0)
__device__ __forceinline__ void cp16(unsigned d, const void* s, bool v) {
    asm volatile("cp.async.ca.shared.global [%0], [%1], 16, %2;"
                 :: "r"(d), "l"(s), "r"(v ? 16 : 0));
}

// ============================================================================
// P1: fp32 -> (hi, lo) bf16 split.  mode 0: src = x -> g_xhi/g_xlo
//                                   mode 1: src = g_sup[0] -> g_yhi/g_ylo
// ============================================================================
__global__ __launch_bounds__(256) void conv_split_kernel(const float* __restrict__ xin,
                                                         int mode)
{
    const float* src = mode ? (const float*)g_sup[0] : xin;
    __nv_bfloat16* hi = mode ? g_yhi : g_xhi;
    __nv_bfloat16* lo = mode ? g_ylo : g_xlo;
    int i4 = blockIdx.x * 256 + threadIdx.x;
    float4 v = ((const float4*)src)[i4];
    __nv_bfloat16 h0 = __float2bfloat16(v.x), h1 = __float2bfloat16(v.y);
    __nv_bfloat16 h2 = __float2bfloat16(v.z), h3 = __float2bfloat16(v.w);
    __nv_bfloat16 l0 = __float2bfloat16(v.x - __bfloat162float(h0));
    __nv_bfloat16 l1 = __float2bfloat16(v.y - __bfloat162float(h1));
    __nv_bfloat16 l2 = __float2bfloat16(v.z - __bfloat162float(h2));
    __nv_bfloat16 l3 = __float2bfloat16(v.w - __bfloat162float(h3));
    ((__nv_bfloat162*)hi)[i4 * 2]     = __nv_bfloat162(h0, h1);
    ((__nv_bfloat162*)hi)[i4 * 2 + 1] = __nv_bfloat162(h2, h3);
    ((__nv_bfloat162*)lo)[i4 * 2]     = __nv_bfloat162(l0, l1);
    ((__nv_bfloat162*)lo)[i4 * 2 + 1] = __nv_bfloat162(l2, l3);
}

// ============================================================================
// P2: W_z -> transposed (hi, lo) bf16: g_w*[z][n][k] = split(W_z[k][n]).
// ============================================================================
__global__ __launch_bounds__(256) void conv_w_kernel(
    const float* __restrict__ W0, const float* __restrict__ W1,
    const float* __restrict__ W2, const float* __restrict__ W3,
    const float* __restrict__ W4)
{
    int id = blockIdx.x * 256 + threadIdx.x;
    int z = id >> 16, rem = id & 65535;
    int n = rem >> 8, k = rem & 255;
    const float* W = (z == 0) ? W0 : (z == 1) ? W1 : (z == 2) ? W2 : (z == 3) ? W3 : W4;
    float v = W[k * DIM + n];
    __nv_bfloat16 h = __float2bfloat16(v);
    g_whi[id] = h;
    g_wlo[id] = __float2bfloat16(v - __bfloat162float(h));
}

// ============================================================================
// K1/K2 GEMM core: HMMA, 3-term bf16 split, cp.async double-buffered.
// mode 0: C[z] = x @ W_z           (A = g_xhi/lo, B = g_w*, C = g_sup[z])
// mode 1: M = y @ Xwin^T           (A = g_yhi/lo, B = g_x* rows m0-64+n0+r,
//                                   OOB rows zero-filled, C = g_raw)
// CTA: 128x128 tile, 8 warps (warp tile 32x64), K chunks of 32, 2 stages.
// ============================================================================
#define KK 32
#define AS 40                      // smem row stride in bf16 -> conflict-free frags
#define SM_ELE (128 * AS)          // 5120 bf16 = 10240 B per part
#define STAGE_B (4 * SM_ELE * 2)   // 40960 B per stage
#define GEMM_DSMEM (2 * STAGE_B)   // 81920 B

__global__ __launch_bounds__(256) void gemm_mma_kernel(int mode, int N)
{
    extern __shared__ __nv_bfloat16 dynsm[];
    const unsigned sb = smem_u32(dynsm);

    const int tid = threadIdx.x;
    const int warp = tid >> 5, lane = tid & 31;
    const int g = lane >> 2, tg = lane & 3;
    const int wm = warp & 3, wn = warp >> 2;

    const int m0 = blockIdx.x * 128;
    const int n0 = blockIdx.y * 128;
    const int z = blockIdx.z;

    const __nv_bfloat16* aH = mode ? g_yhi : g_xhi;
    const __nv_bfloat16* aL = mode ? g_ylo : g_xlo;
    const __nv_bfloat16* bH = mode ? g_xhi : g_whi + (size_t)z * DIM * DIM;
    const __nv_bfloat16* bL = mode ? g_xlo : g_wlo + (size_t)z * DIM * DIM;
    float* C = mode ? g_raw : g_sup[z];
    const int brow0 = mode ? (m0 - WHALF + n0) : n0;
    const int bmax  = mode ? N : 256;

    auto fill = [&](int st, int k0) {
        unsigned base = sb + st * STAGE_B;
#pragma unroll
        for (int q = 0; q < 2; q++) {
            int e = tid + q * 256;
            int r = e >> 2, kq = (e & 3) * 8;
            unsigned so = (unsigned)(r * AS + kq) * 2;
            size_t ga = (size_t)(m0 + r) * DIM + k0 + kq;
            cp16(base + so, aH + ga, true);
            cp16(base + SM_ELE * 2 + so, aL + ga, true);
            int br = brow0 + r;
            bool bv = (br >= 0) && (br < bmax);
            size_t gb = (size_t)(bv ? br : 0) * DIM + k0 + kq;
            cp16(base + 2 * SM_ELE * 2 + so, bH + gb, bv);
            cp16(base + 3 * SM_ELE * 2 + so, bL + gb, bv);
        }
        asm volatile("cp.async.commit_group;" ::: "memory");
    };

    float c[2][8][4];
#pragma unroll
    for (int mf = 0; mf < 2; mf++)
#pragma unroll
        for (int nf = 0; nf < 8; nf++)
#pragma unroll
            for (int q = 0; q < 4; q++) c[mf][nf][q] = 0.f;

    fill(0, 0);

#pragma unroll 1
    for (int ci = 0; ci < DIM / KK; ci++) {
        if (ci + 1 < DIM / KK) {
            fill((ci + 1) & 1, (ci + 1) * KK);
            asm volatile("cp.async.wait_group 1;" ::: "memory");
        } else {
            asm volatile("cp.async.wait_group 0;" ::: "memory");
        }
        __syncthreads();

        const __nv_bfloat16* sAh = dynsm + (ci & 1) * (4 * SM_ELE);
        const __nv_bfloat16* sAl = sAh + SM_ELE;
        const __nv_bfloat16* sBh = sAh + 2 * SM_ELE;
        const __nv_bfloat16* sBl = sAh + 3 * SM_ELE;

#pragma unroll
        for (int ks = 0; ks < KK; ks += 16) {
            unsigned bh[8][2], bl[8][2];
#pragma unroll
            for (int nf = 0; nf < 8; nf++) {
                int bn = wn * 64 + nf * 8 + g;
                int o = bn * AS + ks + tg * 2;
                bh[nf][0] = *(const unsigned*)&sBh[o];
                bh[nf][1] = *(const unsigned*)&sBh[o + 8];
                bl[nf][0] = *(const unsigned*)&sBl[o];
                bl[nf][1] = *(const unsigned*)&sBl[o + 8];
            }
#pragma unroll
            for (int mf = 0; mf < 2; mf++) {
                int ar = wm * 32 + mf * 16 + g;
                int o = ar * AS + ks + tg * 2;
                unsigned ah[4], al[4];
                ah[0] = *(const unsigned*)&sAh[o];
                ah[1] = *(const unsigned*)&sAh[o + 8 * AS];
                ah[2] = *(const unsigned*)&sAh[o + 8];
                ah[3] = *(const unsigned*)&sAh[o + 8 * AS + 8];
                al[0] = *(const unsigned*)&sAl[o];
                al[1] = *(const unsigned*)&sAl[o + 8 * AS];
                al[2] = *(const unsigned*)&sAl[o + 8];
                al[3] = *(const unsigned*)&sAl[o + 8 * AS + 8];
#pragma unroll
                for (int nf = 0; nf < 8; nf++) {
                    MMA16816(c[mf][nf], ah, bh[nf]);
                    MMA16816(c[mf][nf], ah, bl[nf]);
                    MMA16816(c[mf][nf], al, bh[nf]);
                }
            }
        }
        __syncthreads();
    }

#pragma unroll
    for (int mf = 0; mf < 2; mf++) {
#pragma unroll
        for (int nf = 0; nf < 8; nf++) {
            int row = m0 + wm * 32 + mf * 16 + g;
            int col = n0 + wn * 64 + nf * 8 + tg * 2;
            *(float2*)&C[(size_t)row * DIM + col] =
                make_float2(c[mf][nf][0], c[mf][nf][1]);
            *(float2*)&C[(size_t)(row + 8) * DIM + col] =
                make_float2(c[mf][nf][2], c[mf][nf][3]);
        }
    }
}

// ============================================================================
// K2b: band-extract softmax. raw[i][w] = g_raw[i][(i%128) + w], softmax over w.
// One warp per row; lane handles slots {lane, lane+32, lane+64, lane+96}.
// ============================================================================
__global__ __launch_bounds__(256) void bandsm_kernel()
{
    const int wid = threadIdx.x >> 5, lane = threadIdx.x & 31;
    const int i = blockIdx.x * 8 + wid;
    const float* row = g_raw + (size_t)i * DIM + (i & 127);

    float v0 = row[lane];
    float v1 = row[lane + 32];
    float v2 = row[lane + 64];
    float v3 = row[lane + 96];
    float mx = fmaxf(fmaxf(v0, v1), fmaxf(v2, v3));
#pragma unroll
    for (int o = 16; o; o >>= 1)
        mx = fmaxf(mx, __shfl_xor_sync(0xffffffffu, mx, o));
    float e0 = expf(v0 - mx), e1 = expf(v1 - mx);
    float e2 = expf(v2 - mx), e3 = expf(v3 - mx);
    float s = e0 + e1 + e2 + e3;
#pragma unroll
    for (int o = 16; o; o >>= 1)
        s += __shfl_xor_sync(0xffffffffu, s, o);
    float inv = 1.f / s;
    size_t base = (size_t)i * WIN;
    g_attn[base + lane]      = e0 * inv;
    g_attn[base + lane + 32] = e1 * inv;
    g_attn[base + lane + 64] = e2 * inv;
    g_attn[base + lane + 96] = e3 * inv;
}

// ============================================================================
// K3: banded relation aggregation (j-major, supports loaded once per tile).
// ============================================================================
#define K3_TI 32
#define K3_JW 160
__global__ __launch_bounds__(128) void agg_kernel(
    const int* __restrict__ spk, int N)
{
    __shared__ float c_base[K3_TI * K3_JW];
    __shared__ float c_eq[K3_TI * K3_JW];

    const int i0 = blockIdx.x * K3_TI;
    const int t = threadIdx.x;

    for (int e = t; e < K3_TI * K3_JW; e += 128) {
        int i = e / K3_JW;
        int jj = e - i * K3_JW;
        int j = i0 - WHALF + jj;
        int w = jj - i;
        bool ok = (w >= 0) && (w < WIN) && (j >= 0) && (j < N);
        float a = ok ? g_attn[(size_t)(i0 + i) * WIN + w] : 0.f;
        c_base[e] = a;
        c_eq[e] = (ok && spk[j] == spk[i0 + i]) ? a : 0.f;
    }
    __syncthreads();

    const float* P  = g_sup[1];
    const float* S  = g_sup[2];
    const float* SM = g_sup[3];
    const float* DF = g_sup[4];
    const int d2 = t * 2;

    float2 acc[K3_TI];
#pragma unroll
    for (int i = 0; i < K3_TI; i++) { acc[i].x = 0.f; acc[i].y = 0.f; }

    for (int jj = 0; jj < K3_JW; jj++) {
        int j = i0 - WHALF + jj;
        if (j < 0 || j >= N) continue;
        size_t idx = (size_t)j * DIM + d2;
        float2 p  = *(const float2*)(P + idx);
        float2 s  = *(const float2*)(S + idx);
        float2 sm = *(const float2*)(SM + idx);
        float2 df = *(const float2*)(DF + idx);
        float2 diff = make_float2(sm.x - df.x, sm.y - df.y);
        float2 pd   = make_float2(p.x + df.x, p.y + df.y);
        float2 sd   = make_float2(s.x + df.x, s.y + df.y);
        int isplit = jj - WHALF;
#pragma unroll
        for (int i = 0; i < K3_TI; i++) {
            float c  = c_base[i * K3_JW + jj];
            float ce = c_eq[i * K3_JW + jj];
            bool pred = (i <= isplit);
            float bx = pred ? pd.x : sd.x;
            float by = pred ? pd.y : sd.y;
            acc[i].x += c * bx + ce * diff.x;
            acc[i].y += c * by + ce * diff.y;
        }
    }

#pragma unroll
    for (int i = 0; i < K3_TI; i++)
        *(float2*)(g_h + (size_t)(i0 + i) * DIM + d2) = acc[i];
}

// ============================================================================
// K4: row-wise log_softmax over D=256.
// ============================================================================
__global__ __launch_bounds__(256) void lsm_kernel(float* __restrict__ out)
{
    __shared__ float red[8];
    __shared__ float bcast;

    const int i = blockIdx.x;
    const int t = threadIdx.x;
    const int wid = t >> 5, lane = t & 31;

    float v = g_h[(size_t)i * DIM + t];

    float m = v;
#pragma unroll
    for (int o = 16; o; o >>= 1)
        m = fmaxf(m, __shfl_xor_sync(0xffffffffu, m, o));
    if (lane == 0) red[wid] = m;
    __syncthreads();
    if (t < 32) {
        float xr = (t < 8) ? red[t] : -INFINITY;
#pragma unroll
        for (int o = 4; o; o >>= 1)
            xr = fmaxf(xr, __shfl_xor_sync(0xffffffffu, xr, o));
        if (t == 0) bcast = xr;
    }
    __syncthreads();
    float mx = bcast;

    float e = expf(v - mx);
    float sum = e;
#pragma unroll
    for (int o = 16; o; o >>= 1)
        sum += __shfl_xor_sync(0xffffffffu, sum, o);
    if (lane == 0) red[wid] = sum;
    __syncthreads();
    if (t < 32) {
        float xr = (t < 8) ? red[t] : 0.f;
#pragma unroll
        for (int o = 4; o; o >>= 1)
            xr += __shfl_xor_sync(0xffffffffu, xr, o);
        if (t == 0) bcast = logf(xr);
    }
    __syncthreads();
    float lse = bcast;

    out[(size_t)i * DIM + t] = v - mx - lse;
}

// ============================================================================
// launch
// ============================================================================
extern "C" void kernel_launch(void* const* d_in, const int* in_sizes, int n_in,
                              void* d_out, int out_size)
{
    const float* x      = (const float*)d_in[0];
    const int*   spk    = (const int*)d_in[1];
    const float* W_att  = (const float*)d_in[2];
    const float* W_pred = (const float*)d_in[3];
    const float* W_suc  = (const float*)d_in[4];
    const float* W_same = (const float*)d_in[5];
    const float* W_diff = (const float*)d_in[6];
    float* out = (float*)d_out;

    const int N = in_sizes[1];   // speaker_ids element count == N

    cudaFuncSetAttribute(gemm_mma_kernel,
                         cudaFuncAttributeMaxDynamicSharedMemorySize, GEMM_DSMEM);

    // P1/P2: bf16 hi/lo conversions
    conv_split_kernel<<<(N * DIM / 4) / 256, 256>>>(x, 0);
    conv_w_kernel<<<(5 * DIM * DIM) / 256, 256>>>(W_att, W_pred, W_suc, W_same, W_diff);

    // K1: HMMA GEMMs (y_att + 4 supports)
    gemm_mma_kernel<<<dim3(N / 128, DIM / 128, 5), 256, GEMM_DSMEM>>>(0, N);

    // K2: y -> bf16, banded attention as one more GEMM unit, band softmax
    conv_split_kernel<<<(N * DIM / 4) / 256, 256>>>(x, 1);
    gemm_mma_kernel<<<dim3(N / 128, DIM / 128, 1), 256, GEMM_DSMEM>>>(1, N);
    bandsm_kernel<<<N / 8, 256>>>();

    // K3: banded relation aggregation
    agg_kernel<<<N / K3_TI, 128>>>(spk, N);
    // K4: log_softmax
    lsm_kernel<<<N, 256>>>(out);
}